// round 2
// baseline (speedup 1.0000x reference)
#include <cuda_runtime.h>
#include <math.h>

#define BB 4
#define NN 2048
#define CC 256
#define HH 8
#define LL 2
#define RAD2 0.09f
#define EPSV 1e-5f
#define NROWS (BB*NN)
#define EG 64
#define KG 33
#define GROWS (EG*KG)

__device__ float g_x [NROWS*CC];
__device__ float g_q [NROWS*CC];
__device__ float g_k [NROWS*CC];
__device__ float g_v [NROWS*CC];
__device__ float g_ao[NROWS*CC];
__device__ float g_pr[NROWS*CC];
__device__ float g_z1[NROWS*64];
__device__ float g_z2[NROWS*32];
__device__ float g_z3[NROWS*16];
__device__ float g_mu1[64],  g_var1[64];
__device__ float g_mu2[32],  g_var2[32];
__device__ float g_mu3[16],  g_var3[16];
__device__ int   g_idx[EG];
__device__ float g_grouped[GROWS*3];
__device__ float g_zg1[GROWS*64];
__device__ float g_zg2[GROWS*256];
__device__ float g_zg3[GROWS*512];
__device__ float g_mug1[64],  g_varg1[64];
__device__ float g_mug2[256], g_varg2[256];
__device__ float g_mug3[512], g_varg3[512];

// (B,C,N) -> (B,N,C)
__global__ __launch_bounds__(256) void k_transpose(const float* __restrict__ src,
                                                   float* __restrict__ dst) {
    __shared__ float t[32][33];
    int b = blockIdx.z, n0 = blockIdx.x*32, c0 = blockIdx.y*32;
    int tx = threadIdx.x, ty = threadIdx.y;
    #pragma unroll
    for (int i = 0; i < 32; i += 8)
        t[ty+i][tx] = src[((size_t)b*CC + c0 + ty + i)*NN + n0 + tx];
    __syncthreads();
    #pragma unroll
    for (int i = 0; i < 32; i += 8)
        dst[((size_t)b*NN + n0 + ty + i)*CC + c0 + tx] = t[tx][ty+i];
}

// C = A(MxK) @ B(KxN), all row-major
__global__ __launch_bounds__(256) void k_gemm(const float* __restrict__ A,
                                              const float* __restrict__ B,
                                              float* __restrict__ C,
                                              int M, int Nc, int Kd) {
    __shared__ float As[16][64];
    __shared__ float Bs[16][64];
    int bm = blockIdx.x*64, bn = blockIdx.y*64;
    int tid = threadIdx.x;
    int tr = tid >> 4, tc = tid & 15;
    int arow = tid >> 2, ak = (tid & 3) << 2;
    int brow = tid >> 4, bc = (tid & 15) << 2;
    float acc[4][4];
    #pragma unroll
    for (int i = 0; i < 4; i++)
        #pragma unroll
        for (int j = 0; j < 4; j++) acc[i][j] = 0.f;
    for (int k0 = 0; k0 < Kd; k0 += 16) {
        float4 av = *(const float4*)(A + (size_t)(bm+arow)*Kd + k0 + ak);
        As[ak+0][arow]=av.x; As[ak+1][arow]=av.y; As[ak+2][arow]=av.z; As[ak+3][arow]=av.w;
        *(float4*)&Bs[brow][bc] = *(const float4*)(B + (size_t)(k0+brow)*Nc + bn + bc);
        __syncthreads();
        #pragma unroll
        for (int kk = 0; kk < 16; kk++) {
            float4 a = *(const float4*)&As[kk][tr<<2];
            float4 b = *(const float4*)&Bs[kk][tc<<2];
            acc[0][0]+=a.x*b.x; acc[0][1]+=a.x*b.y; acc[0][2]+=a.x*b.z; acc[0][3]+=a.x*b.w;
            acc[1][0]+=a.y*b.x; acc[1][1]+=a.y*b.y; acc[1][2]+=a.y*b.z; acc[1][3]+=a.y*b.w;
            acc[2][0]+=a.z*b.x; acc[2][1]+=a.z*b.y; acc[2][2]+=a.z*b.z; acc[2][3]+=a.z*b.w;
            acc[3][0]+=a.w*b.x; acc[3][1]+=a.w*b.y; acc[3][2]+=a.w*b.z; acc[3][3]+=a.w*b.w;
        }
        __syncthreads();
    }
    #pragma unroll
    for (int i = 0; i < 4; i++)
        *(float4*)(C + (size_t)(bm+(tr<<2)+i)*Nc + bn + (tc<<2)) =
            make_float4(acc[i][0],acc[i][1],acc[i][2],acc[i][3]);
}

// flash attention: grid(16 qtiles, H, B), 256 thr
__global__ __launch_bounds__(256) void k_flash(const float* __restrict__ Q,
                                               const float* __restrict__ K,
                                               const float* __restrict__ V,
                                               float* __restrict__ O) {
    extern __shared__ float sm[];
    float* Qs = sm;               // [32][128] d-major
    float* Ks = Qs + 32*128;      // [32][64]  d-major
    float* Vs = Ks + 32*64;       // [64][32]
    float* Ss = Vs + 64*32;       // [128][68]
    float* m_s = Ss + 128*68;
    float* l_s = m_s + 128;
    float* c_s = l_s + 128;
    int tid = threadIdx.x;
    int qt = blockIdx.x, h = blockIdx.y, b = blockIdx.z;
    const size_t rowbase = (size_t)b*NN + (size_t)qt*128;
    const float* qb = Q + rowbase*CC + h*32;
    const float* kb = K + (size_t)b*NN*CC + h*32;
    const float* vb = V + (size_t)b*NN*CC + h*32;

    for (int i = tid; i < 128*8; i += 256) {
        int r = i >> 3, d4 = (i & 7) << 2;
        float4 v = *(const float4*)(qb + (size_t)r*CC + d4);
        Qs[(d4+0)*128+r]=v.x; Qs[(d4+1)*128+r]=v.y; Qs[(d4+2)*128+r]=v.z; Qs[(d4+3)*128+r]=v.w;
    }
    if (tid < 128) { m_s[tid] = -3.0e30f; l_s[tid] = 0.f; }
    int tr8 = (tid >> 4) * 8;
    int tc4 = (tid & 15) * 4;
    int tc2 = (tid & 15) * 2;
    float oa[8][2];
    #pragma unroll
    for (int r = 0; r < 8; r++) { oa[r][0]=0.f; oa[r][1]=0.f; }
    __syncthreads();

    for (int c0 = 0; c0 < NN; c0 += 64) {
        for (int i = tid; i < 64*8; i += 256) {
            int r = i >> 3, d4 = (i & 7) << 2;
            float4 kv = *(const float4*)(kb + (size_t)(c0+r)*CC + d4);
            Ks[(d4+0)*64+r]=kv.x; Ks[(d4+1)*64+r]=kv.y; Ks[(d4+2)*64+r]=kv.z; Ks[(d4+3)*64+r]=kv.w;
            *(float4*)(Vs + r*32 + d4) = *(const float4*)(vb + (size_t)(c0+r)*CC + d4);
        }
        __syncthreads();
        float s[8][4];
        #pragma unroll
        for (int r = 0; r < 8; r++) { s[r][0]=0.f; s[r][1]=0.f; s[r][2]=0.f; s[r][3]=0.f; }
        #pragma unroll
        for (int d = 0; d < 32; d++) {
            float4 a0 = *(const float4*)(Qs + d*128 + tr8);
            float4 a1 = *(const float4*)(Qs + d*128 + tr8 + 4);
            float4 bb = *(const float4*)(Ks + d*64 + tc4);
            float av[8] = {a0.x,a0.y,a0.z,a0.w,a1.x,a1.y,a1.z,a1.w};
            #pragma unroll
            for (int r = 0; r < 8; r++) {
                s[r][0]+=av[r]*bb.x; s[r][1]+=av[r]*bb.y;
                s[r][2]+=av[r]*bb.z; s[r][3]+=av[r]*bb.w;
            }
        }
        const float scale = 0.1767766952966369f;
        #pragma unroll
        for (int r = 0; r < 8; r++)
            *(float4*)(Ss + (size_t)(tr8+r)*68 + tc4) =
                make_float4(s[r][0]*scale, s[r][1]*scale, s[r][2]*scale, s[r][3]*scale);
        __syncthreads();
        {
            int row = tid >> 1, half = tid & 1;
            float* srow = Ss + (size_t)row*68 + half*32;
            float mx = -3.0e30f;
            #pragma unroll
            for (int j = 0; j < 32; j++) mx = fmaxf(mx, srow[j]);
            mx = fmaxf(mx, __shfl_xor_sync(0xffffffffu, mx, 1));
            float mold = m_s[row];
            float mnew = fmaxf(mold, mx);
            float corr = __expf(mold - mnew);
            float sum = 0.f;
            #pragma unroll
            for (int j = 0; j < 32; j++) { float p = __expf(srow[j] - mnew); srow[j] = p; sum += p; }
            sum += __shfl_xor_sync(0xffffffffu, sum, 1);
            if (!half) { l_s[row] = l_s[row]*corr + sum; m_s[row] = mnew; c_s[row] = corr; }
        }
        __syncthreads();
        #pragma unroll
        for (int r = 0; r < 8; r++) { float f = c_s[tr8+r]; oa[r][0]*=f; oa[r][1]*=f; }
        #pragma unroll 4
        for (int j0 = 0; j0 < 64; j0 += 4) {
            float2 v0 = *(const float2*)(Vs + (j0+0)*32 + tc2);
            float2 v1 = *(const float2*)(Vs + (j0+1)*32 + tc2);
            float2 v2 = *(const float2*)(Vs + (j0+2)*32 + tc2);
            float2 v3 = *(const float2*)(Vs + (j0+3)*32 + tc2);
            #pragma unroll
            for (int r = 0; r < 8; r++) {
                float4 p = *(const float4*)(Ss + (size_t)(tr8+r)*68 + j0);
                oa[r][0] += p.x*v0.x + p.y*v1.x + p.z*v2.x + p.w*v3.x;
                oa[r][1] += p.x*v0.y + p.y*v1.y + p.z*v2.y + p.w*v3.y;
            }
        }
        __syncthreads();
    }
    #pragma unroll
    for (int r = 0; r < 8; r++) {
        int row = tr8 + r;
        float inv = 1.f / l_s[row];
        *(float2*)(O + (rowbase+row)*CC + h*32 + tc2) = make_float2(oa[r][0]*inv, oa[r][1]*inv);
    }
}

__global__ __launch_bounds__(256) void k_lnres(const float* __restrict__ xin,
                                               const float* __restrict__ o,
                                               const float* __restrict__ g,
                                               const float* __restrict__ bta,
                                               float* __restrict__ xout) {
    int row = blockIdx.x*8 + threadIdx.y;
    int lane = threadIdx.x;
    const float* xr = xin + (size_t)row*CC;
    const float* orr = o + (size_t)row*CC;
    float v[8]; float s = 0.f;
    #pragma unroll
    for (int i = 0; i < 8; i++) { int c = lane + i*32; v[i] = xr[c] + orr[c]; s += v[i]; }
    #pragma unroll
    for (int off = 16; off; off >>= 1) s += __shfl_xor_sync(0xffffffffu, s, off);
    float mean = s * (1.f/256.f);
    float vs = 0.f;
    #pragma unroll
    for (int i = 0; i < 8; i++) { float d = v[i]-mean; vs += d*d; }
    #pragma unroll
    for (int off = 16; off; off >>= 1) vs += __shfl_xor_sync(0xffffffffu, vs, off);
    float rstd = rsqrtf(vs*(1.f/256.f) + EPSV);
    #pragma unroll
    for (int i = 0; i < 8; i++) {
        int c = lane + i*32;
        xout[(size_t)row*CC + c] = (v[i]-mean)*rstd*g[c] + bta[c];
    }
}

__global__ __launch_bounds__(256) void k_stats(const float* __restrict__ z, int rows, int C,
                                               float* __restrict__ mu, float* __restrict__ var) {
    int c = blockIdx.x, tid = threadIdx.x;
    float s = 0.f, sq = 0.f;
    for (int r = tid; r < rows; r += 256) {
        float v = z[(size_t)r*C + c]; s += v; sq += v*v;
    }
    __shared__ float ss[256], qq[256];
    ss[tid] = s; qq[tid] = sq;
    __syncthreads();
    for (int off = 128; off; off >>= 1) {
        if (tid < off) { ss[tid]+=ss[tid+off]; qq[tid]+=qq[tid+off]; }
        __syncthreads();
    }
    if (tid == 0) {
        float m = ss[0]/rows;
        mu[c] = m; var[c] = fmaxf(qq[0]/rows - m*m, 0.f);
    }
}

// out[r,o] = act(bn(in[r,:])) dot w[o,:] (+bias); act 0=id,1=relu,2=lrelu
__global__ __launch_bounds__(256) void k_dense(const float* __restrict__ in, int Cin,
                                               const float* __restrict__ w,
                                               const float* __restrict__ bias,
                                               const float* __restrict__ mu,
                                               const float* __restrict__ var,
                                               const float* __restrict__ gam,
                                               const float* __restrict__ bet,
                                               int act,
                                               float* __restrict__ out, int Cout) {
    __shared__ float a_s[32*256];
    int rowbase = blockIdx.x*32;
    int tid = threadIdx.x;
    for (int i = tid; i < 32*Cin; i += 256) {
        int r = i / Cin, c = i - r*Cin;
        float v = in[(size_t)(rowbase+r)*Cin + c];
        if (act) {
            float sc = gam[c]*rsqrtf(var[c]+EPSV);
            v = (v - mu[c])*sc + bet[c];
            v = (act == 1) ? fmaxf(v, 0.f) : (v > 0.f ? v : 0.2f*v);
        }
        a_s[i] = v;
    }
    __syncthreads();
    int npairs = Cout*4;
    for (int pr = tid; pr < npairs; pr += 256) {
        int o = pr % Cout, rb = (pr / Cout)*8;
        float bz = bias ? bias[o] : 0.f;
        float acc[8];
        #pragma unroll
        for (int r = 0; r < 8; r++) acc[r] = bz;
        const float* wr = w + (size_t)o*Cin;
        for (int c = 0; c < Cin; c += 4) {
            float4 wv = *(const float4*)(wr + c);
            #pragma unroll
            for (int r = 0; r < 8; r++) {
                float4 av = *(const float4*)(a_s + (rb+r)*Cin + c);
                acc[r] += wv.x*av.x + wv.y*av.y + wv.z*av.z + wv.w*av.w;
            }
        }
        #pragma unroll
        for (int r = 0; r < 8; r++)
            out[(size_t)(rowbase+rb+r)*Cout + o] = acc[r];
    }
}

__global__ __launch_bounds__(256) void k_argmax(const float* __restrict__ z3,
                                                const float* __restrict__ mu,
                                                const float* __restrict__ var,
                                                const float* __restrict__ gam,
                                                const float* __restrict__ bet,
                                                int* __restrict__ idx) {
    int bc = blockIdx.x;
    int b = bc >> 4, c = bc & 15;
    int tid = threadIdx.x;
    float sc = gam[c]*rsqrtf(var[c]+EPSV);
    float sh = bet[c] - mu[c]*sc;
    float best = -1.f; int bi = 1 << 30;
    for (int n = tid; n < NN; n += 256) {
        float v = fmaxf(z3[(size_t)(b*NN+n)*16 + c]*sc + sh, 0.f);
        if (v > best) { best = v; bi = n; }
    }
    __shared__ float bv[256]; __shared__ int bx[256];
    bv[tid] = best; bx[tid] = bi;
    __syncthreads();
    for (int off = 128; off; off >>= 1) {
        if (tid < off) {
            if (bv[tid+off] > bv[tid] || (bv[tid+off] == bv[tid] && bx[tid+off] < bx[tid])) {
                bv[tid] = bv[tid+off]; bx[tid] = bx[tid+off];
            }
        }
        __syncthreads();
    }
    if (tid == 0) idx[bc] = bx[0];
}

__global__ void k_ballq(const float* __restrict__ pts, const int* __restrict__ idx,
                        float* __restrict__ grouped) {
    int e = blockIdx.x;
    int b = e >> 4;
    int lane = threadIdx.x;
    const float* px = pts + (size_t)b*3*NN;
    int qi = idx[e];
    float qx = px[qi], qy = px[NN+qi], qz = px[2*NN+qi];
    float qq = qx*qx + qy*qy + qz*qz;
    __shared__ int gi[32];
    int cnt = 0;
    for (int base = 0; base < NN && cnt < 32; base += 32) {
        int n = base + lane;
        float x = px[n], y = px[NN+n], z = px[2*NN+n];
        float pp = x*x + y*y + z*z;
        float d = qq + pp - 2.f*(qx*x + qy*y + qz*z);
        bool in = !(d > RAD2);
        unsigned m = __ballot_sync(0xffffffffu, in);
        int pos = cnt + __popc(m & ((1u << lane) - 1u));
        if (in && pos < 32) gi[pos] = n;
        cnt += __popc(m);
    }
    __syncwarp();
    if (cnt > 32) cnt = 32;
    int g0 = gi[0];
    int g = (lane < cnt) ? gi[lane] : g0;
    if (lane == 0) {
        grouped[(size_t)e*KG*3+0] = qx;
        grouped[(size_t)e*KG*3+1] = qy;
        grouped[(size_t)e*KG*3+2] = qz;
    }
    size_t o = ((size_t)e*KG + 1 + lane)*3;
    grouped[o+0] = px[g]; grouped[o+1] = px[NN+g]; grouped[o+2] = px[2*NN+g];
}

__global__ __launch_bounds__(256) void k_gc1(const float* __restrict__ grouped,
                                             const float* __restrict__ w,
                                             float* __restrict__ out) {
    int i = blockIdx.x*256 + threadIdx.x;
    if (i >= GROWS*64) return;
    int o = i & 63, r = i >> 6;
    const float* p = grouped + (size_t)r*3;
    const float* wr = w + o*3;
    out[i] = wr[0]*p[0] + wr[1]*p[1] + wr[2]*p[2];
}

__global__ __launch_bounds__(256) void k_finalmax(const float* __restrict__ zg3,
                                                  const float* __restrict__ mu,
                                                  const float* __restrict__ var,
                                                  const float* __restrict__ gam,
                                                  const float* __restrict__ bet,
                                                  float* __restrict__ out) {
    int i = blockIdx.x*256 + threadIdx.x;  // over B*512*16
    if (i >= BB*512*16) return;
    int s = i & 15, c = (i >> 4) & 511, b = i >> 13;
    int e = b*16 + s;
    float sc = gam[c]*rsqrtf(var[c]+EPSV);
    float sh = bet[c] - mu[c]*sc;
    float mx = -3.0e30f;
    const float* base = zg3 + (size_t)e*KG*512 + c;
    #pragma unroll 1
    for (int k = 0; k < KG; k++) {
        float v = base[(size_t)k*512]*sc + sh;
        v = (v > 0.f) ? v : 0.2f*v;
        mx = fmaxf(mx, v);
    }
    out[((size_t)b*512 + c)*16 + s] = mx;
}

extern "C" void kernel_launch(void* const* d_in, const int* in_sizes, int n_in,
                              void* d_out, int out_size) {
    const float* hoch = (const float*)d_in[0];
    const float* pts  = (const float*)d_in[1];
    const float* Wq   = (const float*)d_in[2];
    const float* Wk   = (const float*)d_in[3];
    const float* Wv   = (const float*)d_in[4];
    const float* Wo   = (const float*)d_in[5];
    const float* ln_g = (const float*)d_in[6];
    const float* ln_b = (const float*)d_in[7];
    const float* fgw1 = (const float*)d_in[8];
    const float* fgb1 = (const float*)d_in[9];
    const float* fgw2 = (const float*)d_in[10];
    const float* fgb2 = (const float*)d_in[11];
    const float* fgw3 = (const float*)d_in[12];
    const float* fgb3 = (const float*)d_in[13];
    const float* fgg1 = (const float*)d_in[14];
    const float* fge1 = (const float*)d_in[15];
    const float* fgg2 = (const float*)d_in[16];
    const float* fge2 = (const float*)d_in[17];
    const float* fgg3 = (const float*)d_in[18];
    const float* fge3 = (const float*)d_in[19];
    const float* cw1  = (const float*)d_in[20];
    const float* cw2  = (const float*)d_in[21];
    const float* cw3  = (const float*)d_in[22];
    const float* cg1  = (const float*)d_in[23];
    const float* cb1  = (const float*)d_in[24];
    const float* cg2  = (const float*)d_in[25];
    const float* cb2  = (const float*)d_in[26];
    const float* cg3  = (const float*)d_in[27];
    const float* cb3  = (const float*)d_in[28];
    float* out = (float*)d_out;

    void* a;
    cudaGetSymbolAddress(&a, g_x);       float* x   = (float*)a;
    cudaGetSymbolAddress(&a, g_q);       float* q   = (float*)a;
    cudaGetSymbolAddress(&a, g_k);       float* k   = (float*)a;
    cudaGetSymbolAddress(&a, g_v);       float* v   = (float*)a;
    cudaGetSymbolAddress(&a, g_ao);      float* ao  = (float*)a;
    cudaGetSymbolAddress(&a, g_pr);      float* pr  = (float*)a;
    cudaGetSymbolAddress(&a, g_z1);      float* z1  = (float*)a;
    cudaGetSymbolAddress(&a, g_z2);      float* z2  = (float*)a;
    cudaGetSymbolAddress(&a, g_z3);      float* z3  = (float*)a;
    cudaGetSymbolAddress(&a, g_mu1);     float* mu1 = (float*)a;
    cudaGetSymbolAddress(&a, g_var1);    float* va1 = (float*)a;
    cudaGetSymbolAddress(&a, g_mu2);     float* mu2 = (float*)a;
    cudaGetSymbolAddress(&a, g_var2);    float* va2 = (float*)a;
    cudaGetSymbolAddress(&a, g_mu3);     float* mu3 = (float*)a;
    cudaGetSymbolAddress(&a, g_var3);    float* va3 = (float*)a;
    cudaGetSymbolAddress(&a, g_idx);     int*   idx = (int*)a;
    cudaGetSymbolAddress(&a, g_grouped); float* grp = (float*)a;
    cudaGetSymbolAddress(&a, g_zg1);     float* zg1 = (float*)a;
    cudaGetSymbolAddress(&a, g_zg2);     float* zg2 = (float*)a;
    cudaGetSymbolAddress(&a, g_zg3);     float* zg3 = (float*)a;
    cudaGetSymbolAddress(&a, g_mug1);    float* mg1 = (float*)a;
    cudaGetSymbolAddress(&a, g_varg1);   float* vg1 = (float*)a;
    cudaGetSymbolAddress(&a, g_mug2);    float* mg2 = (float*)a;
    cudaGetSymbolAddress(&a, g_varg2);   float* vg2 = (float*)a;
    cudaGetSymbolAddress(&a, g_mug3);    float* mg3 = (float*)a;
    cudaGetSymbolAddress(&a, g_varg3);   float* vg3 = (float*)a;

    const int SMEM_FLASH = (32*128 + 32*64 + 64*32 + 128*68 + 3*128) * 4;
    cudaFuncSetAttribute(k_flash, cudaFuncAttributeMaxDynamicSharedMemorySize, SMEM_FLASH);

    k_transpose<<<dim3(NN/32, CC/32, BB), dim3(32,8)>>>(hoch, x);

    for (int l = 0; l < LL; l++) {
        const float* wq = Wq + (size_t)l*CC*CC;
        const float* wk = Wk + (size_t)l*CC*CC;
        const float* wv = Wv + (size_t)l*CC*CC;
        const float* wo = Wo + (size_t)l*CC*CC;
        k_gemm<<<dim3(NROWS/64, CC/64), 256>>>(x, wq, q, NROWS, CC, CC);
        k_gemm<<<dim3(NROWS/64, CC/64), 256>>>(x, wk, k, NROWS, CC, CC);
        k_gemm<<<dim3(NROWS/64, CC/64), 256>>>(x, wv, v, NROWS, CC, CC);
        k_flash<<<dim3(16, HH, BB), 256, SMEM_FLASH>>>(q, k, v, ao);
        k_gemm<<<dim3(NROWS/64, CC/64), 256>>>(ao, wo, pr, NROWS, CC, CC);
        k_lnres<<<NROWS/8, dim3(32,8)>>>(x, pr, ln_g + l*CC, ln_b + l*CC, x);
    }

    k_dense<<<NROWS/32, 256>>>(x, 256, fgw1, fgb1, 0, 0, 0, 0, 0, z1, 64);
    k_stats<<<64, 256>>>(z1, NROWS, 64, mu1, va1);
    k_dense<<<NROWS/32, 256>>>(z1, 64, fgw2, fgb2, mu1, va1, fgg1, fge1, 1, z2, 32);
    k_stats<<<32, 256>>>(z2, NROWS, 32, mu2, va2);
    k_dense<<<NROWS/32, 256>>>(z2, 32, fgw3, fgb3, mu2, va2, fgg2, fge2, 1, z3, 16);
    k_stats<<<16, 256>>>(z3, NROWS, 16, mu3, va3);
    k_argmax<<<EG, 256>>>(z3, mu3, va3, fgg3, fge3, idx);

    k_ballq<<<EG, 32>>>(pts, idx, grp);
    k_gc1<<<(GROWS*64 + 255)/256, 256>>>(grp, cw1, zg1);
    k_stats<<<64, 256>>>(zg1, GROWS, 64, mg1, vg1);
    k_dense<<<GROWS/32, 256>>>(zg1, 64, cw2, 0, mg1, vg1, cg1, cb1, 2, zg2, 256);
    k_stats<<<256, 256>>>(zg2, GROWS, 256, mg2, vg2);
    k_dense<<<GROWS/32, 256>>>(zg2, 256, cw3, 0, mg2, vg2, cg2, cb2, 2, zg3, 512);
    k_stats<<<512, 256>>>(zg3, GROWS, 512, mg3, vg3);
    k_finalmax<<<(BB*512*16 + 255)/256, 256>>>(zg3, mg3, vg3, cg3, cb3, out);
}

// round 3
// speedup vs baseline: 1.1961x; 1.1961x over previous
#include <cuda_runtime.h>
#include <math.h>

#define BB 4
#define NN 2048
#define CC 256
#define HH 8
#define LL 2
#define RAD2 0.09f
#define EPSV 1e-5f
#define NROWS (BB*NN)
#define EG 64
#define KG 33
#define GROWS (EG*KG)

__device__ float g_x [NROWS*CC];
__device__ float g_q [NROWS*CC];
__device__ float g_k [NROWS*CC];
__device__ float g_v [NROWS*CC];
__device__ float g_ao[NROWS*CC];
__device__ float g_pr[NROWS*CC];
__device__ float g_z1[NROWS*64];
__device__ float g_z2[NROWS*32];
__device__ float g_z3[NROWS*16];
__device__ float g_mu1[64],  g_var1[64];
__device__ float g_mu2[32],  g_var2[32];
__device__ float g_mu3[16],  g_var3[16];
__device__ int   g_idx[EG];
__device__ float g_grouped[GROWS*3];
__device__ float g_zg1[GROWS*64];
__device__ float g_zg2[GROWS*256];
__device__ float g_zg3[GROWS*512];
__device__ float g_mug1[64],  g_varg1[64];
__device__ float g_mug2[256], g_varg2[256];
__device__ float g_mug3[512], g_varg3[512];

// ---------------- tf32 helpers ----------------
__device__ __forceinline__ uint2 tf32x2(float x) {
    unsigned hi, lo;
    asm("cvt.rna.tf32.f32 %0, %1;" : "=r"(hi) : "f"(x));
    float r = x - __uint_as_float(hi);
    asm("cvt.rna.tf32.f32 %0, %1;" : "=r"(lo) : "f"(r));
    return make_uint2(hi, lo);
}

__device__ __forceinline__ void mma8(float* d,
                                     unsigned a0, unsigned a1, unsigned a2, unsigned a3,
                                     unsigned b0, unsigned b1) {
    asm volatile("mma.sync.aligned.m16n8k8.row.col.f32.tf32.tf32.f32 "
        "{%0,%1,%2,%3}, {%4,%5,%6,%7}, {%8,%9}, {%0,%1,%2,%3};"
        : "+f"(d[0]), "+f"(d[1]), "+f"(d[2]), "+f"(d[3])
        : "r"(a0), "r"(a1), "r"(a2), "r"(a3), "r"(b0), "r"(b1));
}

// tf32x3: (ah+al)*(bh+bl) ~= ah*bh + ah*bl + al*bh  (error ~2^-22, ~fp32)
__device__ __forceinline__ void mma_x3(float* d, const uint2* a, uint2 b0, uint2 b1) {
    mma8(d, a[0].x, a[1].x, a[2].x, a[3].x, b0.x, b1.x);
    mma8(d, a[0].x, a[1].x, a[2].x, a[3].x, b0.y, b1.y);
    mma8(d, a[0].y, a[1].y, a[2].y, a[3].y, b0.x, b1.x);
}

// ---------------- (B,C,N) -> (B,N,C) ----------------
__global__ __launch_bounds__(256) void k_transpose(const float* __restrict__ src,
                                                   float* __restrict__ dst) {
    __shared__ float t[32][33];
    int b = blockIdx.z, n0 = blockIdx.x*32, c0 = blockIdx.y*32;
    int tx = threadIdx.x, ty = threadIdx.y;
    #pragma unroll
    for (int i = 0; i < 32; i += 8)
        t[ty+i][tx] = src[((size_t)b*CC + c0 + ty + i)*NN + n0 + tx];
    __syncthreads();
    #pragma unroll
    for (int i = 0; i < 32; i += 8)
        dst[((size_t)b*NN + n0 + ty + i)*CC + c0 + tx] = t[tx][ty+i];
}

// ---------------- tf32x3 GEMM: C(MxN) = A(MxK) @ B(KxN), row-major ----------
// grid (M/128, N/64), 256 threads (8 warps: 4 m-groups x 2 n-halves)
__global__ __launch_bounds__(256) void k_gemm_t(const float* __restrict__ A,
                                                const float* __restrict__ B,
                                                float* __restrict__ C,
                                                int Kd, int Nc) {
    __shared__ float As[128][36];
    __shared__ float Bs[32][72];
    int tid = threadIdx.x;
    int w = tid >> 5, lane = tid & 31, g = lane >> 2, tg = lane & 3;
    int mt = w >> 1, nh = w & 1;
    int bm = blockIdx.x*128, bn = blockIdx.y*64;
    float acc[2][4][4];
    #pragma unroll
    for (int m = 0; m < 2; m++)
        #pragma unroll
        for (int nt = 0; nt < 4; nt++)
            #pragma unroll
            for (int i = 0; i < 4; i++) acc[m][nt][i] = 0.f;

    for (int k0 = 0; k0 < Kd; k0 += 32) {
        for (int i = tid; i < 128*8; i += 256) {
            int r = i >> 3, c = (i & 7) << 2;
            *(float4*)&As[r][c] = *(const float4*)(A + (size_t)(bm+r)*Kd + k0 + c);
        }
        for (int i = tid; i < 32*16; i += 256) {
            int r = i >> 4, c = (i & 15) << 2;
            *(float4*)&Bs[r][c] = *(const float4*)(B + (size_t)(k0+r)*Nc + bn + c);
        }
        __syncthreads();
        #pragma unroll
        for (int kk = 0; kk < 4; kk++) {
            int kb = kk*8;
            uint2 af[2][4];
            #pragma unroll
            for (int m = 0; m < 2; m++) {
                int r0 = mt*32 + m*16 + g;
                af[m][0] = tf32x2(As[r0  ][kb+tg]);
                af[m][1] = tf32x2(As[r0+8][kb+tg]);
                af[m][2] = tf32x2(As[r0  ][kb+tg+4]);
                af[m][3] = tf32x2(As[r0+8][kb+tg+4]);
            }
            #pragma unroll
            for (int nt = 0; nt < 4; nt++) {
                int n0 = nh*32 + nt*8;
                uint2 b0 = tf32x2(Bs[kb+tg  ][n0+g]);
                uint2 b1 = tf32x2(Bs[kb+tg+4][n0+g]);
                mma_x3(acc[0][nt], af[0], b0, b1);
                mma_x3(acc[1][nt], af[1], b0, b1);
            }
        }
        __syncthreads();
    }
    #pragma unroll
    for (int m = 0; m < 2; m++)
        #pragma unroll
        for (int nt = 0; nt < 4; nt++) {
            int row = bm + mt*32 + m*16 + g;
            int col = bn + nh*32 + nt*8 + 2*tg;
            *(float2*)(C + (size_t)row*Nc + col) = make_float2(acc[m][nt][0], acc[m][nt][1]);
            *(float2*)(C + (size_t)(row+8)*Nc + col) = make_float2(acc[m][nt][2], acc[m][nt][3]);
        }
}

// ---------------- flash attention, tf32x3 tensor-core ----------------------
// 64 queries x 64-key chunks, dh=32. grid (NN/64, H, B), 256 thr (8 warps).
// warp w: mt=w>>1 -> rows 16*mt..+15 ; nh=w&1 -> S-cols / key-half 32*nh..+31
__global__ __launch_bounds__(256) void k_flash(const float* __restrict__ Q,
                                               const float* __restrict__ K,
                                               const float* __restrict__ V,
                                               float* __restrict__ O) {
    __shared__ float Qs[64][36];
    __shared__ float Ks[64][36];
    __shared__ float Vs[64][40];
    __shared__ float Ss[64][68];
    __shared__ float m_s[64], l_s[64], c_s[64];

    int tid = threadIdx.x;
    int w = tid >> 5, lane = tid & 31, g = lane >> 2, tg = lane & 3;
    int mt = w >> 1, nh = w & 1;
    int qt = blockIdx.x, h = blockIdx.y, b = blockIdx.z;
    const size_t rowbase = (size_t)b*NN + (size_t)qt*64;
    const float* qb = Q + rowbase*CC + h*32;
    const float* kb = K + (size_t)b*NN*CC + h*32;
    const float* vb = V + (size_t)b*NN*CC + h*32;

    for (int i = tid; i < 64*8; i += 256) {
        int r = i >> 3, c = (i & 7) << 2;
        *(float4*)&Qs[r][c] = *(const float4*)(qb + (size_t)r*CC + c);
    }
    if (tid < 64) { m_s[tid] = -3.0e30f; l_s[tid] = 0.f; }
    __syncthreads();

    const float scale = 0.1767766952966369f;  // 1/sqrt(32)
    int r0 = mt*16 + g;
    uint2 qf[4][4];
    #pragma unroll
    for (int kk = 0; kk < 4; kk++) {
        int kbk = kk*8;
        qf[kk][0] = tf32x2(Qs[r0  ][kbk+tg]   * scale);
        qf[kk][1] = tf32x2(Qs[r0+8][kbk+tg]   * scale);
        qf[kk][2] = tf32x2(Qs[r0  ][kbk+tg+4] * scale);
        qf[kk][3] = tf32x2(Qs[r0+8][kbk+tg+4] * scale);
    }

    float of[4][4];
    #pragma unroll
    for (int nt = 0; nt < 4; nt++)
        #pragma unroll
        for (int i = 0; i < 4; i++) of[nt][i] = 0.f;

    for (int c0 = 0; c0 < NN; c0 += 64) {
        for (int i = tid; i < 64*8; i += 256) {
            int r = i >> 3, c = (i & 7) << 2;
            *(float4*)&Ks[r][c] = *(const float4*)(kb + (size_t)(c0+r)*CC + c);
            *(float4*)&Vs[r][c] = *(const float4*)(vb + (size_t)(c0+r)*CC + c);
        }
        __syncthreads();

        // S = (Q*scale) @ K^T  (warp covers rows r0/r0+8, cols nh*32..+31)
        float sacc[4][4];
        #pragma unroll
        for (int nt = 0; nt < 4; nt++) {
            #pragma unroll
            for (int i = 0; i < 4; i++) sacc[nt][i] = 0.f;
            int n0 = nh*32 + nt*8;
            #pragma unroll
            for (int kk = 0; kk < 4; kk++) {
                int kbk = kk*8;
                uint2 b0 = tf32x2(Ks[n0+g][kbk+tg]);
                uint2 b1 = tf32x2(Ks[n0+g][kbk+tg+4]);
                mma_x3(sacc[nt], qf[kk], b0, b1);
            }
        }
        #pragma unroll
        for (int nt = 0; nt < 4; nt++) {
            int n0 = nh*32 + nt*8 + 2*tg;
            *(float2*)&Ss[r0  ][n0] = make_float2(sacc[nt][0], sacc[nt][1]);
            *(float2*)&Ss[r0+8][n0] = make_float2(sacc[nt][2], sacc[nt][3]);
        }
        __syncthreads();

        // online softmax: 4 threads per row, 16 cols each
        {
            int row = tid >> 2, qq = tid & 3;
            float* srow = &Ss[row][qq*16];
            float mx = -3.0e30f;
            #pragma unroll
            for (int j = 0; j < 16; j++) mx = fmaxf(mx, srow[j]);
            mx = fmaxf(mx, __shfl_xor_sync(0xffffffffu, mx, 1));
            mx = fmaxf(mx, __shfl_xor_sync(0xffffffffu, mx, 2));
            float mold = m_s[row];
            float mnew = fmaxf(mold, mx);
            float sum = 0.f;
            #pragma unroll
            for (int j = 0; j < 16; j++) {
                float p = __expf(srow[j] - mnew);
                srow[j] = p; sum += p;
            }
            sum += __shfl_xor_sync(0xffffffffu, sum, 1);
            sum += __shfl_xor_sync(0xffffffffu, sum, 2);
            if (qq == 0) {
                float corr = __expf(mold - mnew);
                c_s[row] = corr;
                l_s[row] = l_s[row]*corr + sum;
                m_s[row] = mnew;
            }
        }
        __syncthreads();

        // rescale O, then O += P(half) @ V(half)
        {
            float cr0 = c_s[r0], cr1 = c_s[r0+8];
            #pragma unroll
            for (int nt = 0; nt < 4; nt++) {
                of[nt][0] *= cr0; of[nt][1] *= cr0;
                of[nt][2] *= cr1; of[nt][3] *= cr1;
            }
        }
        uint2 pa[4][4];
        #pragma unroll
        for (int kk = 0; kk < 4; kk++) {
            int k0 = nh*32 + kk*8;
            pa[kk][0] = tf32x2(Ss[r0  ][k0+tg]);
            pa[kk][1] = tf32x2(Ss[r0+8][k0+tg]);
            pa[kk][2] = tf32x2(Ss[r0  ][k0+tg+4]);
            pa[kk][3] = tf32x2(Ss[r0+8][k0+tg+4]);
        }
        #pragma unroll
        for (int nt = 0; nt < 4; nt++) {
            int n0 = nt*8;
            #pragma unroll
            for (int kk = 0; kk < 4; kk++) {
                int k0 = nh*32 + kk*8;
                uint2 b0 = tf32x2(Vs[k0+tg  ][n0+g]);
                uint2 b1 = tf32x2(Vs[k0+tg+4][n0+g]);
                mma_x3(of[nt], pa[kk], b0, b1);
            }
        }
        __syncthreads();
    }

    // combine the two key-halves, divide by l, write out
    if (nh == 1) {
        #pragma unroll
        for (int nt = 0; nt < 4; nt++) {
            int c = nt*8 + 2*tg;
            *(float2*)&Ss[r0  ][c] = make_float2(of[nt][0], of[nt][1]);
            *(float2*)&Ss[r0+8][c] = make_float2(of[nt][2], of[nt][3]);
        }
    }
    __syncthreads();
    if (nh == 0) {
        float inv0 = 1.f / l_s[r0], inv1 = 1.f / l_s[r0+8];
        #pragma unroll
        for (int nt = 0; nt < 4; nt++) {
            int c = nt*8 + 2*tg;
            float2 p0 = *(float2*)&Ss[r0  ][c];
            float2 p1 = *(float2*)&Ss[r0+8][c];
            *(float2*)(O + (rowbase + r0)*CC + h*32 + c) =
                make_float2((of[nt][0]+p0.x)*inv0, (of[nt][1]+p0.y)*inv0);
            *(float2*)(O + (rowbase + r0 + 8)*CC + h*32 + c) =
                make_float2((of[nt][2]+p1.x)*inv1, (of[nt][3]+p1.y)*inv1);
        }
    }
}

__global__ __launch_bounds__(256) void k_lnres(const float* __restrict__ xin,
                                               const float* __restrict__ o,
                                               const float* __restrict__ g,
                                               const float* __restrict__ bta,
                                               float* __restrict__ xout) {
    int row = blockIdx.x*8 + threadIdx.y;
    int lane = threadIdx.x;
    const float* xr = xin + (size_t)row*CC;
    const float* orr = o + (size_t)row*CC;
    float v[8]; float s = 0.f;
    #pragma unroll
    for (int i = 0; i < 8; i++) { int c = lane + i*32; v[i] = xr[c] + orr[c]; s += v[i]; }
    #pragma unroll
    for (int off = 16; off; off >>= 1) s += __shfl_xor_sync(0xffffffffu, s, off);
    float mean = s * (1.f/256.f);
    float vs = 0.f;
    #pragma unroll
    for (int i = 0; i < 8; i++) { float d = v[i]-mean; vs += d*d; }
    #pragma unroll
    for (int off = 16; off; off >>= 1) vs += __shfl_xor_sync(0xffffffffu, vs, off);
    float rstd = rsqrtf(vs*(1.f/256.f) + EPSV);
    #pragma unroll
    for (int i = 0; i < 8; i++) {
        int c = lane + i*32;
        xout[(size_t)row*CC + c] = (v[i]-mean)*rstd*g[c] + bta[c];
    }
}

__global__ __launch_bounds__(256) void k_stats(const float* __restrict__ z, int rows, int C,
                                               float* __restrict__ mu, float* __restrict__ var) {
    int c = blockIdx.x, tid = threadIdx.x;
    float s = 0.f, sq = 0.f;
    for (int r = tid; r < rows; r += 256) {
        float v = z[(size_t)r*C + c]; s += v; sq += v*v;
    }
    __shared__ float ss[256], qq[256];
    ss[tid] = s; qq[tid] = sq;
    __syncthreads();
    for (int off = 128; off; off >>= 1) {
        if (tid < off) { ss[tid]+=ss[tid+off]; qq[tid]+=qq[tid+off]; }
        __syncthreads();
    }
    if (tid == 0) {
        float m = ss[0]/rows;
        mu[c] = m; var[c] = fmaxf(qq[0]/rows - m*m, 0.f);
    }
}

__global__ __launch_bounds__(256) void k_dense(const float* __restrict__ in, int Cin,
                                               const float* __restrict__ w,
                                               const float* __restrict__ bias,
                                               const float* __restrict__ mu,
                                               const float* __restrict__ var,
                                               const float* __restrict__ gam,
                                               const float* __restrict__ bet,
                                               int act,
                                               float* __restrict__ out, int Cout) {
    __shared__ float a_s[32*256];
    int rowbase = blockIdx.x*32;
    int tid = threadIdx.x;
    for (int i = tid; i < 32*Cin; i += 256) {
        int r = i / Cin, c = i - r*Cin;
        float v = in[(size_t)(rowbase+r)*Cin + c];
        if (act) {
            float sc = gam[c]*rsqrtf(var[c]+EPSV);
            v = (v - mu[c])*sc + bet[c];
            v = (act == 1) ? fmaxf(v, 0.f) : (v > 0.f ? v : 0.2f*v);
        }
        a_s[i] = v;
    }
    __syncthreads();
    int npairs = Cout*4;
    for (int pr = tid; pr < npairs; pr += 256) {
        int o = pr % Cout, rb = (pr / Cout)*8;
        float bz = bias ? bias[o] : 0.f;
        float acc[8];
        #pragma unroll
        for (int r = 0; r < 8; r++) acc[r] = bz;
        const float* wr = w + (size_t)o*Cin;
        for (int c = 0; c < Cin; c += 4) {
            float4 wv = *(const float4*)(wr + c);
            #pragma unroll
            for (int r = 0; r < 8; r++) {
                float4 av = *(const float4*)(a_s + (rb+r)*Cin + c);
                acc[r] += wv.x*av.x + wv.y*av.y + wv.z*av.z + wv.w*av.w;
            }
        }
        #pragma unroll
        for (int r = 0; r < 8; r++)
            out[(size_t)(rowbase+rb+r)*Cout + o] = acc[r];
    }
}

__global__ __launch_bounds__(256) void k_argmax(const float* __restrict__ z3,
                                                const float* __restrict__ mu,
                                                const float* __restrict__ var,
                                                const float* __restrict__ gam,
                                                const float* __restrict__ bet,
                                                int* __restrict__ idx) {
    int bc = blockIdx.x;
    int b = bc >> 4, c = bc & 15;
    int tid = threadIdx.x;
    float sc = gam[c]*rsqrtf(var[c]+EPSV);
    float sh = bet[c] - mu[c]*sc;
    float best = -1.f; int bi = 1 << 30;
    for (int n = tid; n < NN; n += 256) {
        float v = fmaxf(z3[(size_t)(b*NN+n)*16 + c]*sc + sh, 0.f);
        if (v > best) { best = v; bi = n; }
    }
    __shared__ float bv[256]; __shared__ int bx[256];
    bv[tid] = best; bx[tid] = bi;
    __syncthreads();
    for (int off = 128; off; off >>= 1) {
        if (tid < off) {
            if (bv[tid+off] > bv[tid] || (bv[tid+off] == bv[tid] && bx[tid+off] < bx[tid])) {
                bv[tid] = bv[tid+off]; bx[tid] = bx[tid+off];
            }
        }
        __syncthreads();
    }
    if (tid == 0) idx[bc] = bx[0];
}

__global__ void k_ballq(const float* __restrict__ pts, const int* __restrict__ idx,
                        float* __restrict__ grouped) {
    int e = blockIdx.x;
    int b = e >> 4;
    int lane = threadIdx.x;
    const float* px = pts + (size_t)b*3*NN;
    int qi = idx[e];
    float qx = px[qi], qy = px[NN+qi], qz = px[2*NN+qi];
    float qq = qx*qx + qy*qy + qz*qz;
    __shared__ int gi[32];
    int cnt = 0;
    for (int base = 0; base < NN && cnt < 32; base += 32) {
        int n = base + lane;
        float x = px[n], y = px[NN+n], z = px[2*NN+n];
        float pp = x*x + y*y + z*z;
        float d = qq + pp - 2.f*(qx*x + qy*y + qz*z);
        bool in = !(d > RAD2);
        unsigned m = __ballot_sync(0xffffffffu, in);
        int pos = cnt + __popc(m & ((1u << lane) - 1u));
        if (in && pos < 32) gi[pos] = n;
        cnt += __popc(m);
    }
    __syncwarp();
    if (cnt > 32) cnt = 32;
    int g0 = gi[0];
    int g = (lane < cnt) ? gi[lane] : g0;
    if (lane == 0) {
        grouped[(size_t)e*KG*3+0] = qx;
        grouped[(size_t)e*KG*3+1] = qy;
        grouped[(size_t)e*KG*3+2] = qz;
    }
    size_t o = ((size_t)e*KG + 1 + lane)*3;
    grouped[o+0] = px[g]; grouped[o+1] = px[NN+g]; grouped[o+2] = px[2*NN+g];
}

__global__ __launch_bounds__(256) void k_gc1(const float* __restrict__ grouped,
                                             const float* __restrict__ w,
                                             float* __restrict__ out) {
    int i = blockIdx.x*256 + threadIdx.x;
    if (i >= GROWS*64) return;
    int o = i & 63, r = i >> 6;
    const float* p = grouped + (size_t)r*3;
    const float* wr = w + o*3;
    out[i] = wr[0]*p[0] + wr[1]*p[1] + wr[2]*p[2];
}

__global__ __launch_bounds__(256) void k_finalmax(const float* __restrict__ zg3,
                                                  const float* __restrict__ mu,
                                                  const float* __restrict__ var,
                                                  const float* __restrict__ gam,
                                                  const float* __restrict__ bet,
                                                  float* __restrict__ out) {
    int i = blockIdx.x*256 + threadIdx.x;
    if (i >= BB*512*16) return;
    int s = i & 15, c = (i >> 4) & 511, b = i >> 13;
    int e = b*16 + s;
    float sc = gam[c]*rsqrtf(var[c]+EPSV);
    float sh = bet[c] - mu[c]*sc;
    float mx = -3.0e30f;
    const float* base = zg3 + (size_t)e*KG*512 + c;
    #pragma unroll 1
    for (int k = 0; k < KG; k++) {
        float v = base[(size_t)k*512]*sc + sh;
        v = (v > 0.f) ? v : 0.2f*v;
        mx = fmaxf(mx, v);
    }
    out[((size_t)b*512 + c)*16 + s] = mx;
}

extern "C" void kernel_launch(void* const* d_in, const int* in_sizes, int n_in,
                              void* d_out, int out_size) {
    const float* hoch = (const float*)d_in[0];
    const float* pts  = (const float*)d_in[1];
    const float* Wq   = (const float*)d_in[2];
    const float* Wk   = (const float*)d_in[3];
    const float* Wv   = (const float*)d_in[4];
    const float* Wo   = (const float*)d_in[5];
    const float* ln_g = (const float*)d_in[6];
    const float* ln_b = (const float*)d_in[7];
    const float* fgw1 = (const float*)d_in[8];
    const float* fgb1 = (const float*)d_in[9];
    const float* fgw2 = (const float*)d_in[10];
    const float* fgb2 = (const float*)d_in[11];
    const float* fgw3 = (const float*)d_in[12];
    const float* fgb3 = (const float*)d_in[13];
    const float* fgg1 = (const float*)d_in[14];
    const float* fge1 = (const float*)d_in[15];
    const float* fgg2 = (const float*)d_in[16];
    const float* fge2 = (const float*)d_in[17];
    const float* fgg3 = (const float*)d_in[18];
    const float* fge3 = (const float*)d_in[19];
    const float* cw1  = (const float*)d_in[20];
    const float* cw2  = (const float*)d_in[21];
    const float* cw3  = (const float*)d_in[22];
    const float* cg1  = (const float*)d_in[23];
    const float* cb1  = (const float*)d_in[24];
    const float* cg2  = (const float*)d_in[25];
    const float* cb2  = (const float*)d_in[26];
    const float* cg3  = (const float*)d_in[27];
    const float* cb3  = (const float*)d_in[28];
    float* out = (float*)d_out;

    void* a;
    cudaGetSymbolAddress(&a, g_x);       float* x   = (float*)a;
    cudaGetSymbolAddress(&a, g_q);       float* q   = (float*)a;
    cudaGetSymbolAddress(&a, g_k);       float* k   = (float*)a;
    cudaGetSymbolAddress(&a, g_v);       float* v   = (float*)a;
    cudaGetSymbolAddress(&a, g_ao);      float* ao  = (float*)a;
    cudaGetSymbolAddress(&a, g_pr);      float* pr  = (float*)a;
    cudaGetSymbolAddress(&a, g_z1);      float* z1  = (float*)a;
    cudaGetSymbolAddress(&a, g_z2);      float* z2  = (float*)a;
    cudaGetSymbolAddress(&a, g_z3);      float* z3  = (float*)a;
    cudaGetSymbolAddress(&a, g_mu1);     float* mu1 = (float*)a;
    cudaGetSymbolAddress(&a, g_var1);    float* va1 = (float*)a;
    cudaGetSymbolAddress(&a, g_mu2);     float* mu2 = (float*)a;
    cudaGetSymbolAddress(&a, g_var2);    float* va2 = (float*)a;
    cudaGetSymbolAddress(&a, g_mu3);     float* mu3 = (float*)a;
    cudaGetSymbolAddress(&a, g_var3);    float* va3 = (float*)a;
    cudaGetSymbolAddress(&a, g_idx);     int*   idx = (int*)a;
    cudaGetSymbolAddress(&a, g_grouped); float* grp = (float*)a;
    cudaGetSymbolAddress(&a, g_zg1);     float* zg1 = (float*)a;
    cudaGetSymbolAddress(&a, g_zg2);     float* zg2 = (float*)a;
    cudaGetSymbolAddress(&a, g_zg3);     float* zg3 = (float*)a;
    cudaGetSymbolAddress(&a, g_mug1);    float* mg1 = (float*)a;
    cudaGetSymbolAddress(&a, g_varg1);   float* vg1 = (float*)a;
    cudaGetSymbolAddress(&a, g_mug2);    float* mg2 = (float*)a;
    cudaGetSymbolAddress(&a, g_varg2);   float* vg2 = (float*)a;
    cudaGetSymbolAddress(&a, g_mug3);    float* mg3 = (float*)a;
    cudaGetSymbolAddress(&a, g_varg3);   float* vg3 = (float*)a;

    k_transpose<<<dim3(NN/32, CC/32, BB), dim3(32,8)>>>(hoch, x);

    for (int l = 0; l < LL; l++) {
        const float* wq = Wq + (size_t)l*CC*CC;
        const float* wk = Wk + (size_t)l*CC*CC;
        const float* wv = Wv + (size_t)l*CC*CC;
        const float* wo = Wo + (size_t)l*CC*CC;
        k_gemm_t<<<dim3(NROWS/128, CC/64), 256>>>(x, wq, q, CC, CC);
        k_gemm_t<<<dim3(NROWS/128, CC/64), 256>>>(x, wk, k, CC, CC);
        k_gemm_t<<<dim3(NROWS/128, CC/64), 256>>>(x, wv, v, CC, CC);
        k_flash<<<dim3(NN/64, HH, BB), 256>>>(q, k, v, ao);
        k_gemm_t<<<dim3(NROWS/128, CC/64), 256>>>(ao, wo, pr, CC, CC);
        k_lnres<<<NROWS/8, dim3(32,8)>>>(x, pr, ln_g + l*CC, ln_b + l*CC, x);
    }

    k_dense<<<NROWS/32, 256>>>(x, 256, fgw1, fgb1, 0, 0, 0, 0, 0, z1, 64);
    k_stats<<<64, 256>>>(z1, NROWS, 64, mu1, va1);
    k_dense<<<NROWS/32, 256>>>(z1, 64, fgw2, fgb2, mu1, va1, fgg1, fge1, 1, z2, 32);
    k_stats<<<32, 256>>>(z2, NROWS, 32, mu2, va2);
    k_dense<<<NROWS/32, 256>>>(z2, 32, fgw3, fgb3, mu2, va2, fgg2, fge2, 1, z3, 16);
    k_stats<<<16, 256>>>(z3, NROWS, 16, mu3, va3);
    k_argmax<<<EG, 256>>>(z3, mu3, va3, fgg3, fge3, idx);

    k_ballq<<<EG, 32>>>(pts, idx, grp);
    k_gc1<<<(GROWS*64 + 255)/256, 256>>>(grp, cw1, zg1);
    k_stats<<<64, 256>>>(zg1, GROWS, 64, mg1, vg1);
    k_dense<<<GROWS/32, 256>>>(zg1, 64, cw2, 0, mg1, vg1, cg1, cb1, 2, zg2, 256);
    k_stats<<<256, 256>>>(zg2, GROWS, 256, mg2, vg2);
    k_dense<<<GROWS/32, 256>>>(zg2, 256, cw3, 0, mg2, vg2, cg2, cb2, 2, zg3, 512);
    k_stats<<<512, 256>>>(zg3, GROWS, 512, mg3, vg3);
    k_finalmax<<<(BB*512*16 + 255)/256, 256>>>(zg3, mg3, vg3, cg3, cb3, out);
}